// round 1
// baseline (speedup 1.0000x reference)
#include <cuda_runtime.h>
#include <math.h>

#define D_MODEL 1024
#define N_HEADS 16
#define DK 64
#define BATCH 2
#define SEQ 2048
#define M_TOT (BATCH * SEQ)   // 4096

// Scratch (allocation-free rule: __device__ globals)
__device__ float g_Q[BATCH * N_HEADS * SEQ * DK];   // [B,H,S,dk]
__device__ float g_K[BATCH * N_HEADS * SEQ * DK];
__device__ float g_V[BATCH * N_HEADS * SEQ * DK];
__device__ float g_ctx[BATCH * SEQ * D_MODEL];      // [B,S,D]

// ---------------------------------------------------------------------------
// GEMM: C = A[M,K] @ W[N,K]^T + bias[N]
// M=4096, N=1024, K=1024. 128x128 block tile, BK=16, 256 threads, 8x8 micro.
// SPLIT=true  -> write into [B,H,S,dk] layout (for Q/K/V projections)
// SPLIT=false -> write into [M,N] row-major (ctx @ Wo^T -> d_out)
// ---------------------------------------------------------------------------
template <bool SPLIT>
__global__ __launch_bounds__(256)
void gemm_bias_kernel(const float* __restrict__ A,
                      const float* __restrict__ W,
                      const float* __restrict__ bias,
                      float* __restrict__ C)
{
    const int K = D_MODEL;
    const int N = D_MODEL;

    __shared__ float As[16][128];
    __shared__ float Bs[16][128];

    const int tid = threadIdx.x;
    const int tx = tid & 15;          // 0..15
    const int ty = tid >> 4;          // 0..15
    const int blockRow = blockIdx.y * 128;
    const int blockCol = blockIdx.x * 128;

    float acc[8][8];
#pragma unroll
    for (int i = 0; i < 8; ++i)
#pragma unroll
        for (int j = 0; j < 8; ++j) acc[i][j] = 0.f;

    for (int k0 = 0; k0 < K; k0 += 16) {
        // load A tile (128 x 16) transposed into As[k][m]
#pragma unroll
        for (int l = 0; l < 2; ++l) {
            int id = tid + l * 256;          // 0..511
            int row = id >> 2;               // 0..127
            int c4 = (id & 3) * 4;           // 0,4,8,12
            float4 v = *(const float4*)(A + (size_t)(blockRow + row) * K + k0 + c4);
            As[c4 + 0][row] = v.x;
            As[c4 + 1][row] = v.y;
            As[c4 + 2][row] = v.z;
            As[c4 + 3][row] = v.w;
        }
        // load W tile (rows = output cols n): Bs[k][n]
#pragma unroll
        for (int l = 0; l < 2; ++l) {
            int id = tid + l * 256;
            int row = id >> 2;
            int c4 = (id & 3) * 4;
            float4 v = *(const float4*)(W + (size_t)(blockCol + row) * K + k0 + c4);
            Bs[c4 + 0][row] = v.x;
            Bs[c4 + 1][row] = v.y;
            Bs[c4 + 2][row] = v.z;
            Bs[c4 + 3][row] = v.w;
        }
        __syncthreads();

#pragma unroll
        for (int kk = 0; kk < 16; ++kk) {
            float a[8], b[8];
#pragma unroll
            for (int i = 0; i < 8; ++i) a[i] = As[kk][ty * 8 + i];
#pragma unroll
            for (int j = 0; j < 8; ++j) b[j] = Bs[kk][tx * 8 + j];
#pragma unroll
            for (int i = 0; i < 8; ++i)
#pragma unroll
                for (int j = 0; j < 8; ++j)
                    acc[i][j] += a[i] * b[j];
        }
        __syncthreads();
    }

#pragma unroll
    for (int i = 0; i < 8; ++i) {
        int m = blockRow + ty * 8 + i;
#pragma unroll
        for (int j = 0; j < 8; ++j) {
            int n = blockCol + tx * 8 + j;
            float val = acc[i][j] + bias[n];
            if (SPLIT) {
                int b_ = m / SEQ;
                int s_ = m - b_ * SEQ;
                int h_ = n / DK;
                int d_ = n - h_ * DK;
                C[(((size_t)(b_ * N_HEADS + h_) * SEQ) + s_) * DK + d_] = val;
            } else {
                C[(size_t)m * N + n] = val;
            }
        }
    }
}

// ---------------------------------------------------------------------------
// Causal flash attention. One CTA = 64 query rows of one (b,h).
// smem: Q tile (64x64), K tile (reused as P), V tile, row stats.
// 256 threads, each owns a 4x4 micro-tile of the 64x64 score/output block.
// ---------------------------------------------------------------------------
#define BQ 64
#define BKV 64
#define TSTR 68                              // padded row stride (floats)
#define FLASH_SMEM_FLOATS (3 * 64 * TSTR + 3 * 64)
#define FLASH_SMEM_BYTES (FLASH_SMEM_FLOATS * 4)

__global__ __launch_bounds__(256)
void flash_attn_kernel()
{
    extern __shared__ float sm[];
    float* Qs = sm;                   // 64 x TSTR
    float* Ks = Qs + 64 * TSTR;       // 64 x TSTR  (recycled as P)
    float* Vs = Ks + 64 * TSTR;       // 64 x TSTR
    float* mrow = Vs + 64 * TSTR;     // 64
    float* lrow = mrow + 64;          // 64
    float* crow = lrow + 64;          // 64

    const int bh = blockIdx.y;                // 0..31
    const int qt = blockIdx.x;                // 0..31
    const int b = bh / N_HEADS;
    const int h = bh - b * N_HEADS;

    const float* Qg = g_Q + (size_t)bh * SEQ * DK;
    const float* Kg = g_K + (size_t)bh * SEQ * DK;
    const float* Vg = g_V + (size_t)bh * SEQ * DK;

    const int tid = threadIdx.x;
    const int tx = tid & 15;
    const int ty = tid >> 4;
    const int q0 = qt * BQ;

    // load Q tile (64 rows x 64 cols): 1024 float4s / 256 threads
#pragma unroll
    for (int l = 0; l < 4; ++l) {
        int id = tid + l * 256;
        int row = id >> 4;
        int c4 = (id & 15) * 4;
        float4 v = *(const float4*)(Qg + (size_t)(q0 + row) * DK + c4);
        *(float4*)(Qs + row * TSTR + c4) = v;
    }
    if (tid < 64) { mrow[tid] = -INFINITY; lrow[tid] = 0.f; }

    float o[4][4];
#pragma unroll
    for (int i = 0; i < 4; ++i)
#pragma unroll
        for (int j = 0; j < 4; ++j) o[i][j] = 0.f;

    const float scale = 0.125f;   // 1/sqrt(64)

    for (int kt = 0; kt <= qt; ++kt) {
        __syncthreads();          // previous PV reads done; Q store / stats init done
        const int k0 = kt * BKV;
#pragma unroll
        for (int l = 0; l < 4; ++l) {
            int id = tid + l * 256;
            int row = id >> 4;
            int c4 = (id & 15) * 4;
            float4 kv = *(const float4*)(Kg + (size_t)(k0 + row) * DK + c4);
            *(float4*)(Ks + row * TSTR + c4) = kv;
            float4 vv = *(const float4*)(Vg + (size_t)(k0 + row) * DK + c4);
            *(float4*)(Vs + row * TSTR + c4) = vv;
        }
        __syncthreads();

        // scores S = Q @ K^T (4x4 per thread, in regs)
        float sacc[4][4];
#pragma unroll
        for (int i = 0; i < 4; ++i)
#pragma unroll
            for (int j = 0; j < 4; ++j) sacc[i][j] = 0.f;

#pragma unroll
        for (int k = 0; k < DK; ++k) {
            float a[4], kb[4];
#pragma unroll
            for (int i = 0; i < 4; ++i) a[i] = Qs[(ty * 4 + i) * TSTR + k];
#pragma unroll
            for (int j = 0; j < 4; ++j) kb[j] = Ks[(tx * 4 + j) * TSTR + k];
#pragma unroll
            for (int i = 0; i < 4; ++i)
#pragma unroll
                for (int j = 0; j < 4; ++j)
                    sacc[i][j] += a[i] * kb[j];
        }
        __syncthreads();          // all K reads done, safe to overwrite Ks with scores

#pragma unroll
        for (int i = 0; i < 4; ++i) {
            int qi = q0 + ty * 4 + i;
#pragma unroll
            for (int j = 0; j < 4; ++j) {
                int kj = k0 + tx * 4 + j;
                Ks[(ty * 4 + i) * TSTR + tx * 4 + j] =
                    (kj <= qi) ? sacc[i][j] * scale : -INFINITY;
            }
        }
        __syncthreads();

        // online softmax row update (one thread per row)
        if (tid < 64) {
            float* Srow = Ks + tid * TSTR;
            float mold = mrow[tid];
            float mmax = mold;
#pragma unroll 8
            for (int c = 0; c < 64; ++c) mmax = fmaxf(mmax, Srow[c]);
            float corr = __expf(mold - mmax);
            float suml = 0.f;
#pragma unroll 8
            for (int c = 0; c < 64; ++c) {
                float p = __expf(Srow[c] - mmax);
                Srow[c] = p;
                suml += p;
            }
            mrow[tid] = mmax;
            lrow[tid] = lrow[tid] * corr + suml;
            crow[tid] = corr;
        }
        __syncthreads();

        // rescale accumulators and O += P @ V
        float cr[4];
#pragma unroll
        for (int i = 0; i < 4; ++i) cr[i] = crow[ty * 4 + i];
#pragma unroll
        for (int i = 0; i < 4; ++i)
#pragma unroll
            for (int j = 0; j < 4; ++j) o[i][j] *= cr[i];

#pragma unroll
        for (int k = 0; k < BKV; ++k) {
            float p[4], v[4];
#pragma unroll
            for (int i = 0; i < 4; ++i) p[i] = Ks[(ty * 4 + i) * TSTR + k];
#pragma unroll
            for (int j = 0; j < 4; ++j) v[j] = Vs[k * TSTR + tx * 4 + j];
#pragma unroll
            for (int i = 0; i < 4; ++i)
#pragma unroll
                for (int j = 0; j < 4; ++j)
                    o[i][j] += p[i] * v[j];
        }
    }

    // finalize: divide by l, write ctx in [B,S,D] layout
    float inv[4];
#pragma unroll
    for (int i = 0; i < 4; ++i) inv[i] = 1.f / lrow[ty * 4 + i];

#pragma unroll
    for (int i = 0; i < 4; ++i) {
        int srow = q0 + ty * 4 + i;
#pragma unroll
        for (int j = 0; j < 4; ++j) {
            g_ctx[((size_t)b * SEQ + srow) * D_MODEL + h * DK + tx * 4 + j] =
                o[i][j] * inv[i];
        }
    }
}

// ---------------------------------------------------------------------------
extern "C" void kernel_launch(void* const* d_in, const int* in_sizes, int n_in,
                              void* d_out, int out_size)
{
    const float* x  = (const float*)d_in[0];
    const float* Wq = (const float*)d_in[1];
    const float* bq = (const float*)d_in[2];
    const float* Wk = (const float*)d_in[3];
    const float* bk = (const float*)d_in[4];
    const float* Wv = (const float*)d_in[5];
    const float* bv = (const float*)d_in[6];
    const float* Wo = (const float*)d_in[7];
    const float* bo = (const float*)d_in[8];
    float* out = (float*)d_out;

    float *pQ, *pK, *pV, *pCtx;
    cudaGetSymbolAddress((void**)&pQ, g_Q);
    cudaGetSymbolAddress((void**)&pK, g_K);
    cudaGetSymbolAddress((void**)&pV, g_V);
    cudaGetSymbolAddress((void**)&pCtx, g_ctx);

    cudaFuncSetAttribute(flash_attn_kernel,
                         cudaFuncAttributeMaxDynamicSharedMemorySize,
                         FLASH_SMEM_BYTES);

    dim3 gemmGrid(D_MODEL / 128, M_TOT / 128);   // (8, 32)
    gemm_bias_kernel<true><<<gemmGrid, 256>>>(x, Wq, bq, pQ);
    gemm_bias_kernel<true><<<gemmGrid, 256>>>(x, Wk, bk, pK);
    gemm_bias_kernel<true><<<gemmGrid, 256>>>(x, Wv, bv, pV);

    dim3 flashGrid(SEQ / BQ, BATCH * N_HEADS);   // (32, 32)
    flash_attn_kernel<<<flashGrid, 256, FLASH_SMEM_BYTES>>>();

    gemm_bias_kernel<false><<<gemmGrid, 256>>>(pCtx, Wo, bo, out);
}

// round 2
// speedup vs baseline: 1.6448x; 1.6448x over previous
#include <cuda_runtime.h>
#include <mma.h>
#include <math.h>

using namespace nvcuda;

#define D_MODEL 1024
#define N_HEADS 16
#define DK 64
#define BATCH 2
#define SEQ 2048
#define M_TOT (BATCH * SEQ)   // 4096

// Scratch (allocation-free rule: __device__ globals)
__device__ float g_Q[BATCH * N_HEADS * SEQ * DK];   // [B,H,S,dk]
__device__ float g_K[BATCH * N_HEADS * SEQ * DK];
__device__ float g_V[BATCH * N_HEADS * SEQ * DK];
__device__ float g_ctx[BATCH * SEQ * D_MODEL];      // [B,S,D]

// ---------------------------------------------------------------------------
// TF32 wmma GEMM: C = A[M,K] @ W[N,K]^T + bias[N]
// M=4096, N=1024, K=1024. Block 128x128, BK=32. 8 warps, warp tile 32x64.
// ---------------------------------------------------------------------------
#define GLDA 36   // smem leading dim for A/B tiles (mult of 4)
#define SLDA 20   // stage leading dim (mult of 4)

template <bool SPLIT>
__global__ __launch_bounds__(256)
void gemm_tf32(const float* __restrict__ A,
               const float* __restrict__ W,
               const float* __restrict__ bias,
               float* __restrict__ C)
{
    __shared__ float As[128][GLDA];          // [m][k]
    __shared__ float Bs[128][GLDA];          // [n][k]  (col-major k x n)
    __shared__ float stage[8][16 * SLDA];

    const int tid = threadIdx.x;
    const int warpId = tid >> 5;
    const int lane = tid & 31;
    const int wm = warpId & 3;       // 0..3  -> 32-row slab
    const int wn = warpId >> 2;      // 0..1  -> 64-col slab
    const int blockRow = blockIdx.y * 128;
    const int blockCol = blockIdx.x * 128;

    wmma::fragment<wmma::accumulator, 16, 16, 8, float> acc[2][4];
#pragma unroll
    for (int i = 0; i < 2; ++i)
#pragma unroll
        for (int j = 0; j < 4; ++j) wmma::fill_fragment(acc[i][j], 0.0f);

    for (int k0 = 0; k0 < D_MODEL; k0 += 32) {
#pragma unroll
        for (int l = 0; l < 4; ++l) {
            int id = tid + l * 256;          // 0..1023
            int row = id >> 3;               // 0..127
            int c4 = (id & 7) * 4;           // 0..28
            *(float4*)&As[row][c4] =
                *(const float4*)(A + (size_t)(blockRow + row) * D_MODEL + k0 + c4);
            *(float4*)&Bs[row][c4] =
                *(const float4*)(W + (size_t)(blockCol + row) * D_MODEL + k0 + c4);
        }
        __syncthreads();

#pragma unroll
        for (int kk = 0; kk < 32; kk += 8) {
            wmma::fragment<wmma::matrix_a, 16, 16, 8, wmma::precision::tf32,
                           wmma::row_major> a[2];
            wmma::fragment<wmma::matrix_b, 16, 16, 8, wmma::precision::tf32,
                           wmma::col_major> b[4];
#pragma unroll
            for (int i = 0; i < 2; ++i) {
                wmma::load_matrix_sync(a[i], &As[wm * 32 + i * 16][kk], GLDA);
#pragma unroll
                for (int e = 0; e < a[i].num_elements; ++e)
                    a[i].x[e] = wmma::__float_to_tf32(a[i].x[e]);
            }
#pragma unroll
            for (int j = 0; j < 4; ++j) {
                wmma::load_matrix_sync(b[j], &Bs[wn * 64 + j * 16][kk], GLDA);
#pragma unroll
                for (int e = 0; e < b[j].num_elements; ++e)
                    b[j].x[e] = wmma::__float_to_tf32(b[j].x[e]);
            }
#pragma unroll
            for (int i = 0; i < 2; ++i)
#pragma unroll
                for (int j = 0; j < 4; ++j)
                    wmma::mma_sync(acc[i][j], a[i], b[j], acc[i][j]);
        }
        __syncthreads();
    }

    // Epilogue: stage each 16x16 tile through private smem, add bias, scatter.
#pragma unroll
    for (int i = 0; i < 2; ++i) {
#pragma unroll
        for (int j = 0; j < 4; ++j) {
            wmma::store_matrix_sync(&stage[warpId][0], acc[i][j], SLDA,
                                    wmma::mem_row_major);
            __syncwarp();
            int r = lane >> 1;
            int cbase = (lane & 1) * 8;
            int m = blockRow + wm * 32 + i * 16 + r;
#pragma unroll
            for (int c = 0; c < 8; ++c) {
                int n = blockCol + wn * 64 + j * 16 + cbase + c;
                float val = stage[warpId][r * SLDA + cbase + c] + __ldg(&bias[n]);
                if (SPLIT) {
                    int b_ = m / SEQ;
                    int s_ = m - b_ * SEQ;
                    int h_ = n / DK;
                    int d_ = n - h_ * DK;
                    C[(((size_t)(b_ * N_HEADS + h_) * SEQ) + s_) * DK + d_] = val;
                } else {
                    C[(size_t)m * D_MODEL + n] = val;
                }
            }
            __syncwarp();
        }
    }
}

// ---------------------------------------------------------------------------
// Causal flash attention with TF32 wmma. One CTA = 64 query rows of one (b,h).
// 256 threads = 8 warps. Warp tile for 64x64 matmuls: 16 (m) x 32 (n).
// ---------------------------------------------------------------------------
#define BQ 64
#define BKV 64
#define FLD 68   // padded leading dim (mult of 4)
#define FLASH_SMEM_FLOATS (5 * 64 * FLD + 2 * 64)
#define FLASH_SMEM_BYTES (FLASH_SMEM_FLOATS * 4)

__global__ __launch_bounds__(256)
void flash_tf32()
{
    extern __shared__ float sm[];
    float* Qs  = sm;                  // [64][FLD]  (row x dk)
    float* Ks  = Qs  + 64 * FLD;      // [64][FLD]  (kv x dk)
    float* Vt  = Ks  + 64 * FLD;      // [64][FLD]  (dk x kv)  transposed V
    float* Ss  = Vt  + 64 * FLD;      // [64][FLD]  scores -> P
    float* PVs = Ss  + 64 * FLD;      // [64][FLD]  P@V tile
    float* mrow = PVs + 64 * FLD;     // [64]
    float* lrow = mrow + 64;          // [64]

    const int bh = blockIdx.y;
    const int qt = blockIdx.x;
    const int b = bh / N_HEADS;
    const int h = bh - b * N_HEADS;

    const float* Qg = g_Q + (size_t)bh * SEQ * DK;
    const float* Kg = g_K + (size_t)bh * SEQ * DK;
    const float* Vg = g_V + (size_t)bh * SEQ * DK;

    const int tid = threadIdx.x;
    const int warpId = tid >> 5;
    const int wm = warpId & 3;        // rows wm*16..+15
    const int wn = warpId >> 2;       // cols wn*32..+31
    const int q0 = qt * BQ;

    // softmax / output ownership: thread -> (row, 16-col slice)
    const int row = tid >> 2;
    const int part = tid & 3;
    const int cbase = part * 16;
    const int qi = q0 + row;

    // load Q tile
#pragma unroll
    for (int l = 0; l < 4; ++l) {
        int id = tid + l * 256;
        int r = id >> 4;
        int c4 = (id & 15) * 4;
        *(float4*)(Qs + r * FLD + c4) =
            *(const float4*)(Qg + (size_t)(q0 + r) * DK + c4);
    }
    if (tid < 64) { mrow[tid] = -INFINITY; lrow[tid] = 0.f; }

    float o[16];
#pragma unroll
    for (int c = 0; c < 16; ++c) o[c] = 0.f;

    const float scale = 0.125f;       // 1/sqrt(64)

    for (int kt = 0; kt <= qt; ++kt) {
        __syncthreads();
        const int k0 = kt * BKV;
        // load K tile; load V transposed
#pragma unroll
        for (int l = 0; l < 4; ++l) {
            int id = tid + l * 256;
            int r = id >> 4;
            int c4 = (id & 15) * 4;
            float4 kv = *(const float4*)(Kg + (size_t)(k0 + r) * DK + c4);
            *(float4*)(Ks + r * FLD + c4) = kv;
            float4 vv = *(const float4*)(Vg + (size_t)(k0 + r) * DK + c4);
            Vt[(c4 + 0) * FLD + r] = vv.x;
            Vt[(c4 + 1) * FLD + r] = vv.y;
            Vt[(c4 + 2) * FLD + r] = vv.z;
            Vt[(c4 + 3) * FLD + r] = vv.w;
        }
        __syncthreads();

        // S = Q @ K^T
        {
            wmma::fragment<wmma::accumulator, 16, 16, 8, float> s0, s1;
            wmma::fill_fragment(s0, 0.0f);
            wmma::fill_fragment(s1, 0.0f);
#pragma unroll
            for (int kk = 0; kk < DK; kk += 8) {
                wmma::fragment<wmma::matrix_a, 16, 16, 8, wmma::precision::tf32,
                               wmma::row_major> a;
                wmma::fragment<wmma::matrix_b, 16, 16, 8, wmma::precision::tf32,
                               wmma::col_major> b0, b1;
                wmma::load_matrix_sync(a, Qs + (wm * 16) * FLD + kk, FLD);
#pragma unroll
                for (int e = 0; e < a.num_elements; ++e)
                    a.x[e] = wmma::__float_to_tf32(a.x[e]);
                wmma::load_matrix_sync(b0, Ks + (wn * 32) * FLD + kk, FLD);
                wmma::load_matrix_sync(b1, Ks + (wn * 32 + 16) * FLD + kk, FLD);
#pragma unroll
                for (int e = 0; e < b0.num_elements; ++e) {
                    b0.x[e] = wmma::__float_to_tf32(b0.x[e]);
                    b1.x[e] = wmma::__float_to_tf32(b1.x[e]);
                }
                wmma::mma_sync(s0, a, b0, s0);
                wmma::mma_sync(s1, a, b1, s1);
            }
            wmma::store_matrix_sync(Ss + (wm * 16) * FLD + wn * 32, s0, FLD,
                                    wmma::mem_row_major);
            wmma::store_matrix_sync(Ss + (wm * 16) * FLD + wn * 32 + 16, s1, FLD,
                                    wmma::mem_row_major);
        }
        __syncthreads();

        // online softmax: 4 threads per row
        float corr;
        {
            float vals[16];
            float mloc = -INFINITY;
#pragma unroll
            for (int c = 0; c < 16; ++c) {
                int kj = k0 + cbase + c;
                float v = (kj <= qi) ? Ss[row * FLD + cbase + c] * scale
                                     : -INFINITY;
                vals[c] = v;
                mloc = fmaxf(mloc, v);
            }
            mloc = fmaxf(mloc, __shfl_xor_sync(0xFFFFFFFF, mloc, 1));
            mloc = fmaxf(mloc, __shfl_xor_sync(0xFFFFFFFF, mloc, 2));
            float mold = mrow[row];
            float lold = lrow[row];
            __syncwarp();
            float mnew = fmaxf(mold, mloc);
            float suml = 0.f;
#pragma unroll
            for (int c = 0; c < 16; ++c) {
                float p = __expf(vals[c] - mnew);   // masked -> exp(-inf)=0
                Ss[row * FLD + cbase + c] = p;
                suml += p;
            }
            suml += __shfl_xor_sync(0xFFFFFFFF, suml, 1);
            suml += __shfl_xor_sync(0xFFFFFFFF, suml, 2);
            corr = __expf(mold - mnew);
            if (part == 0) {
                mrow[row] = mnew;
                lrow[row] = lold * corr + suml;
            }
        }
        __syncthreads();

        // PV = P @ V   (B = Vt, col-major over kv)
        {
            wmma::fragment<wmma::accumulator, 16, 16, 8, float> p0, p1;
            wmma::fill_fragment(p0, 0.0f);
            wmma::fill_fragment(p1, 0.0f);
#pragma unroll
            for (int kk = 0; kk < BKV; kk += 8) {
                wmma::fragment<wmma::matrix_a, 16, 16, 8, wmma::precision::tf32,
                               wmma::row_major> a;
                wmma::fragment<wmma::matrix_b, 16, 16, 8, wmma::precision::tf32,
                               wmma::col_major> b0, b1;
                wmma::load_matrix_sync(a, Ss + (wm * 16) * FLD + kk, FLD);
#pragma unroll
                for (int e = 0; e < a.num_elements; ++e)
                    a.x[e] = wmma::__float_to_tf32(a.x[e]);
                wmma::load_matrix_sync(b0, Vt + (wn * 32) * FLD + kk, FLD);
                wmma::load_matrix_sync(b1, Vt + (wn * 32 + 16) * FLD + kk, FLD);
#pragma unroll
                for (int e = 0; e < b0.num_elements; ++e) {
                    b0.x[e] = wmma::__float_to_tf32(b0.x[e]);
                    b1.x[e] = wmma::__float_to_tf32(b1.x[e]);
                }
                wmma::mma_sync(p0, a, b0, p0);
                wmma::mma_sync(p1, a, b1, p1);
            }
            wmma::store_matrix_sync(PVs + (wm * 16) * FLD + wn * 32, p0, FLD,
                                    wmma::mem_row_major);
            wmma::store_matrix_sync(PVs + (wm * 16) * FLD + wn * 32 + 16, p1, FLD,
                                    wmma::mem_row_major);
        }
        __syncthreads();

        // O = O*corr + PV
#pragma unroll
        for (int c = 0; c < 16; ++c)
            o[c] = o[c] * corr + PVs[row * FLD + cbase + c];
    }

    // finalize
    float linv = 1.f / lrow[row];
#pragma unroll
    for (int c = 0; c < 16; ++c) {
        g_ctx[((size_t)b * SEQ + q0 + row) * D_MODEL + h * DK + cbase + c] =
            o[c] * linv;
    }
}

// ---------------------------------------------------------------------------
extern "C" void kernel_launch(void* const* d_in, const int* in_sizes, int n_in,
                              void* d_out, int out_size)
{
    const float* x  = (const float*)d_in[0];
    const float* Wq = (const float*)d_in[1];
    const float* bq = (const float*)d_in[2];
    const float* Wk = (const float*)d_in[3];
    const float* bk = (const float*)d_in[4];
    const float* Wv = (const float*)d_in[5];
    const float* bv = (const float*)d_in[6];
    const float* Wo = (const float*)d_in[7];
    const float* bo = (const float*)d_in[8];
    float* out = (float*)d_out;

    float *pQ, *pK, *pV, *pCtx;
    cudaGetSymbolAddress((void**)&pQ, g_Q);
    cudaGetSymbolAddress((void**)&pK, g_K);
    cudaGetSymbolAddress((void**)&pV, g_V);
    cudaGetSymbolAddress((void**)&pCtx, g_ctx);

    cudaFuncSetAttribute(flash_tf32,
                         cudaFuncAttributeMaxDynamicSharedMemorySize,
                         FLASH_SMEM_BYTES);

    dim3 gemmGrid(D_MODEL / 128, M_TOT / 128);   // (8, 32)
    gemm_tf32<true><<<gemmGrid, 256>>>(x, Wq, bq, pQ);
    gemm_tf32<true><<<gemmGrid, 256>>>(x, Wk, bk, pK);
    gemm_tf32<true><<<gemmGrid, 256>>>(x, Wv, bv, pV);

    dim3 flashGrid(SEQ / BQ, BATCH * N_HEADS);   // (32, 32)
    flash_tf32<<<flashGrid, 256, FLASH_SMEM_BYTES>>>();

    gemm_tf32<false><<<gemmGrid, 256>>>(pCtx, Wo, bo, out);
}

// round 5
// speedup vs baseline: 2.7009x; 1.6422x over previous
#include <cuda_runtime.h>
#include <cstdint>
#include <mma.h>
#include <math.h>

using namespace nvcuda;

#define D_MODEL 1024
#define N_HEADS 16
#define DK 64
#define BATCH 2
#define SEQ 2048
#define M_TOT (BATCH * SEQ)   // 4096
#define NX (M_TOT * D_MODEL)      // 4,194,304
#define NW (D_MODEL * D_MODEL)    // 1,048,576

// Scratch (allocation-free rule: __device__ globals)
__device__ float g_Q[BATCH * N_HEADS * SEQ * DK];   // [B,H,S,dk] tf32-rounded
__device__ float g_K[BATCH * N_HEADS * SEQ * DK];
__device__ float g_V[BATCH * N_HEADS * SEQ * DK];
__device__ float g_ctx[BATCH * SEQ * D_MODEL];      // [B,S,D]    tf32-rounded
__device__ float g_xr[NX];                          // tf32-rounded x
__device__ float g_Wr[4 * NW];                      // tf32-rounded Wq,Wk,Wv,Wo

__device__ __forceinline__ float rtf32(float a) {
    float r;
    asm("cvt.rna.tf32.f32 %0, %1;" : "=f"(r) : "f"(a));
    return r;
}

// fast exp2 on fma/alu pipes (no MUFU). Input <= 0 (or very negative / masked).
__device__ __forceinline__ float fexp2(float x) {
    x = fmaxf(x, -126.0f);
    float r = rintf(x);
    float f = x - r;                       // [-0.5, 0.5]
    float p = 1.3333558e-3f;
    p = fmaf(p, f, 9.6181291e-3f);
    p = fmaf(p, f, 5.5504109e-2f);
    p = fmaf(p, f, 2.4022651e-1f);
    p = fmaf(p, f, 6.9314718e-1f);
    p = fmaf(p, f, 1.0f);
    return __int_as_float(__float_as_int(p) + (((int)r) << 23));
}

// ---------------------------------------------------------------------------
// Pre-round x and weights to tf32 once.
// ---------------------------------------------------------------------------
__global__ __launch_bounds__(256)
void pre_round_kernel(const float* __restrict__ x,
                      const float* __restrict__ Wq, const float* __restrict__ Wk,
                      const float* __restrict__ Wv, const float* __restrict__ Wo)
{
    int i4 = blockIdx.x * blockDim.x + threadIdx.x;
    const int tot4 = (NX + 4 * NW) / 4;
    if (i4 >= tot4) return;
    int i = i4 * 4;
    const float* src;
    float* dst;
    if (i < NX) { src = x + i; dst = g_xr + i; }
    else {
        int j = i - NX;
        int t = j / NW;
        int o = j - t * NW;
        src = (t == 0 ? Wq : t == 1 ? Wk : t == 2 ? Wv : Wo) + o;
        dst = g_Wr + j;
    }
    float4 v = *(const float4*)src;
    v.x = rtf32(v.x); v.y = rtf32(v.y); v.z = rtf32(v.z); v.w = rtf32(v.w);
    *(float4*)dst = v;
}

// ---------------------------------------------------------------------------
// TF32 wmma GEMM, cp.async 2-stage pipeline: C = A[M,K] @ W[N,K]^T + bias[N]
// A, W pre-rounded to tf32. Block 128x128, BK=32. 8 warps, warp tile 32x64.
// QKV=true: blockIdx.z selects (Wq,bq,Q)/(Wk,bk,K)/(Wv,bv,V), output scattered
//           to [B,H,S,dk] and rounded to tf32.
// ---------------------------------------------------------------------------
#define GLDA 36
#define SLDA 20
#define GEMM_STAGE_FLOATS (128 * GLDA)                 // one stage of one array
#define GEMM_ARR_FLOATS (2 * GEMM_STAGE_FLOATS)        // both stages
#define GEMM_SMEM_FLOATS (2 * GEMM_ARR_FLOATS + 8 * 16 * SLDA)
#define GEMM_SMEM_BYTES (GEMM_SMEM_FLOATS * 4)

__device__ __forceinline__ void cp_async16(unsigned smem_dst, const float* gmem_src) {
    asm volatile("cp.async.cg.shared.global [%0], [%1], 16;\n"
                 :: "r"(smem_dst), "l"(gmem_src));
}

template <bool QKV>
__global__ __launch_bounds__(256)
void gemm_tf32(const float* __restrict__ A,
               const float* __restrict__ W0, const float* __restrict__ W1,
               const float* __restrict__ W2,
               const float* __restrict__ b0, const float* __restrict__ b1,
               const float* __restrict__ b2,
               float* __restrict__ C0, float* __restrict__ C1,
               float* __restrict__ C2)
{
    extern __shared__ float smg[];
    float* As = smg;                         // 2 stages x 128 x GLDA
    float* Bs = As + GEMM_ARR_FLOATS;        // 2 stages x 128 x GLDA
    float* stg = Bs + GEMM_ARR_FLOATS;       // 8 x 16 x SLDA

    const float* W; const float* bias; float* C;
    if (QKV) {
        int z = blockIdx.z;
        W = (z == 0) ? W0 : (z == 1) ? W1 : W2;
        bias = (z == 0) ? b0 : (z == 1) ? b1 : b2;
        C = (z == 0) ? C0 : (z == 1) ? C1 : C2;
    } else { W = W0; bias = b0; C = C0; }

    const int tid = threadIdx.x;
    const int warpId = tid >> 5;
    const int lane = tid & 31;
    const int wm = warpId & 3;
    const int wn = warpId >> 2;
    const int blockRow = blockIdx.y * 128;
    const int blockCol = blockIdx.x * 128;

    const unsigned As_u = (unsigned)__cvta_generic_to_shared(As);
    const unsigned Bs_u = (unsigned)__cvta_generic_to_shared(Bs);

    wmma::fragment<wmma::accumulator, 16, 16, 8, float> acc[2][4];
#pragma unroll
    for (int i = 0; i < 2; ++i)
#pragma unroll
        for (int j = 0; j < 4; ++j) wmma::fill_fragment(acc[i][j], 0.0f);

    // stage loader: 1024 float4s per tile pair, 256 threads -> 4 each per array
    auto load_stage = [&](int s, int k0) {
#pragma unroll
        for (int l = 0; l < 4; ++l) {
            int id = tid + l * 256;          // 0..1023
            int row = id >> 3;               // 0..127
            int c4 = (id & 7) * 4;           // 0..28
            unsigned off = (unsigned)((s * GEMM_STAGE_FLOATS + row * GLDA + c4) * 4);
            cp_async16(As_u + off, A + (size_t)(blockRow + row) * D_MODEL + k0 + c4);
            cp_async16(Bs_u + off, W + (size_t)(blockCol + row) * D_MODEL + k0 + c4);
        }
        asm volatile("cp.async.commit_group;\n" ::);
    };

    load_stage(0, 0);

    const int NT = D_MODEL / 32;             // 32 k-tiles
    for (int t = 0; t < NT; ++t) {
        if (t + 1 < NT) {
            load_stage((t + 1) & 1, (t + 1) * 32);
            asm volatile("cp.async.wait_group 1;\n" ::);
        } else {
            asm volatile("cp.async.wait_group 0;\n" ::);
        }
        __syncthreads();

        const float* Asb = As + (t & 1) * GEMM_STAGE_FLOATS;
        const float* Bsb = Bs + (t & 1) * GEMM_STAGE_FLOATS;
#pragma unroll
        for (int kk = 0; kk < 32; kk += 8) {
            wmma::fragment<wmma::matrix_a, 16, 16, 8, wmma::precision::tf32,
                           wmma::row_major> a[2];
            wmma::fragment<wmma::matrix_b, 16, 16, 8, wmma::precision::tf32,
                           wmma::col_major> b[4];
#pragma unroll
            for (int i = 0; i < 2; ++i)
                wmma::load_matrix_sync(a[i], Asb + (wm * 32 + i * 16) * GLDA + kk, GLDA);
#pragma unroll
            for (int j = 0; j < 4; ++j)
                wmma::load_matrix_sync(b[j], Bsb + (wn * 64 + j * 16) * GLDA + kk, GLDA);
#pragma unroll
            for (int i = 0; i < 2; ++i)
#pragma unroll
                for (int j = 0; j < 4; ++j)
                    wmma::mma_sync(acc[i][j], a[i], b[j], acc[i][j]);
        }
        __syncthreads();
    }

    // Epilogue: stage tiles through private smem, add bias, scatter.
#pragma unroll
    for (int i = 0; i < 2; ++i) {
#pragma unroll
        for (int j = 0; j < 4; ++j) {
            wmma::store_matrix_sync(&stg[warpId * 16 * SLDA], acc[i][j], SLDA,
                                    wmma::mem_row_major);
            __syncwarp();
            int r = lane >> 1;
            int cb = (lane & 1) * 8;
            int m = blockRow + wm * 32 + i * 16 + r;
#pragma unroll
            for (int c = 0; c < 8; ++c) {
                int n = blockCol + wn * 64 + j * 16 + cb + c;
                float val = stg[warpId * 16 * SLDA + r * SLDA + cb + c] + __ldg(&bias[n]);
                if (QKV) {
                    int b_ = m / SEQ;
                    int s_ = m - b_ * SEQ;
                    int h_ = n / DK;
                    int d_ = n - h_ * DK;
                    C[(((size_t)(b_ * N_HEADS + h_) * SEQ) + s_) * DK + d_] = rtf32(val);
                } else {
                    C[(size_t)m * D_MODEL + n] = val;
                }
            }
            __syncwarp();
        }
    }
}

// ---------------------------------------------------------------------------
// Causal flash attention, TF32 wmma, poly-exp2 softmax (no MUFU).
// Q pre-scaled by scale*log2(e) at load. All mma operands pre-rounded.
// ---------------------------------------------------------------------------
#define BQ 64
#define BKV 64
#define FLD 68
#define FLASH_SMEM_FLOATS (5 * 64 * FLD + 2 * 64)
#define FLASH_SMEM_BYTES (FLASH_SMEM_FLOATS * 4)

__global__ __launch_bounds__(256)
void flash_tf32()
{
    extern __shared__ float sm[];
    float* Qs  = sm;                  // [64][FLD]
    float* Ks  = Qs  + 64 * FLD;      // [64][FLD]
    float* Vt  = Ks  + 64 * FLD;      // [64][FLD] transposed V
    float* Ss  = Vt  + 64 * FLD;      // [64][FLD] scores -> P
    float* PVs = Ss  + 64 * FLD;      // [64][FLD]
    float* mrow = PVs + 64 * FLD;
    float* lrow = mrow + 64;

    const int bh = blockIdx.y;
    const int qt = blockIdx.x;
    const int b = bh / N_HEADS;
    const int h = bh - b * N_HEADS;

    const float* Qg = g_Q + (size_t)bh * SEQ * DK;
    const float* Kg = g_K + (size_t)bh * SEQ * DK;
    const float* Vg = g_V + (size_t)bh * SEQ * DK;

    const int tid = threadIdx.x;
    const int warpId = tid >> 5;
    const int wm = warpId & 3;
    const int wn = warpId >> 2;
    const int q0 = qt * BQ;

    const int row = tid >> 2;
    const int part = tid & 3;
    const int cbase = part * 16;
    const int qi = q0 + row;

    const float qscale = 0.125f * 1.44269504089f;  // scale * log2(e)

    // load Q tile, pre-scaled (re-round after scaling)
#pragma unroll
    for (int l = 0; l < 4; ++l) {
        int id = tid + l * 256;
        int r = id >> 4;
        int c4 = (id & 15) * 4;
        float4 v = *(const float4*)(Qg + (size_t)(q0 + r) * DK + c4);
        v.x = rtf32(v.x * qscale); v.y = rtf32(v.y * qscale);
        v.z = rtf32(v.z * qscale); v.w = rtf32(v.w * qscale);
        *(float4*)(Qs + r * FLD + c4) = v;
    }
    if (tid < 64) { mrow[tid] = -1e30f; lrow[tid] = 0.f; }

    float o[16];
#pragma unroll
    for (int c = 0; c < 16; ++c) o[c] = 0.f;

    for (int kt = 0; kt <= qt; ++kt) {
        const int k0 = kt * BKV;
#pragma unroll
        for (int l = 0; l < 4; ++l) {
            int id = tid + l * 256;
            int r = id >> 4;
            int c4 = (id & 15) * 4;
            float4 kv = *(const float4*)(Kg + (size_t)(k0 + r) * DK + c4);
            *(float4*)(Ks + r * FLD + c4) = kv;
            float4 vv = *(const float4*)(Vg + (size_t)(k0 + r) * DK + c4);
            Vt[(c4 + 0) * FLD + r] = vv.x;
            Vt[(c4 + 1) * FLD + r] = vv.y;
            Vt[(c4 + 2) * FLD + r] = vv.z;
            Vt[(c4 + 3) * FLD + r] = vv.w;
        }
        __syncthreads();

        // S = Q @ K^T  (log2-domain scores, scale folded into Q)
        {
            wmma::fragment<wmma::accumulator, 16, 16, 8, float> s0, s1;
            wmma::fill_fragment(s0, 0.0f);
            wmma::fill_fragment(s1, 0.0f);
#pragma unroll
            for (int kk = 0; kk < DK; kk += 8) {
                wmma::fragment<wmma::matrix_a, 16, 16, 8, wmma::precision::tf32,
                               wmma::row_major> a;
                wmma::fragment<wmma::matrix_b, 16, 16, 8, wmma::precision::tf32,
                               wmma::col_major> b0, b1;
                wmma::load_matrix_sync(a, Qs + (wm * 16) * FLD + kk, FLD);
                wmma::load_matrix_sync(b0, Ks + (wn * 32) * FLD + kk, FLD);
                wmma::load_matrix_sync(b1, Ks + (wn * 32 + 16) * FLD + kk, FLD);
                wmma::mma_sync(s0, a, b0, s0);
                wmma::mma_sync(s1, a, b1, s1);
            }
            wmma::store_matrix_sync(Ss + (wm * 16) * FLD + wn * 32, s0, FLD,
                                    wmma::mem_row_major);
            wmma::store_matrix_sync(Ss + (wm * 16) * FLD + wn * 32 + 16, s1, FLD,
                                    wmma::mem_row_major);
        }
        __syncthreads();

        // online softmax (base-2), 4 threads per row, poly exp2
        float corr;
        {
            float vals[16];
            float mloc = -1e30f;
#pragma unroll
            for (int c = 0; c < 16; ++c) {
                int kj = k0 + cbase + c;
                float v = (kj <= qi) ? Ss[row * FLD + cbase + c] : -1e30f;
                vals[c] = v;
                mloc = fmaxf(mloc, v);
            }
            mloc = fmaxf(mloc, __shfl_xor_sync(0xFFFFFFFF, mloc, 1));
            mloc = fmaxf(mloc, __shfl_xor_sync(0xFFFFFFFF, mloc, 2));
            float mold = mrow[row];
            float lold = lrow[row];
            __syncwarp();
            float mnew = fmaxf(mold, mloc);
            float suml = 0.f;
#pragma unroll
            for (int c = 0; c < 16; ++c) {
                float p = fexp2(vals[c] - mnew);
                Ss[row * FLD + cbase + c] = rtf32(p);
                suml += p;
            }
            suml += __shfl_xor_sync(0xFFFFFFFF, suml, 1);
            suml += __shfl_xor_sync(0xFFFFFFFF, suml, 2);
            corr = fexp2(mold - mnew);
            if (part == 0) {
                mrow[row] = mnew;
                lrow[row] = lold * corr + suml;
            }
        }
        __syncthreads();

        // PV = P @ V
        {
            wmma::fragment<wmma::accumulator, 16, 16, 8, float> p0, p1;
            wmma::fill_fragment(p0, 0.0f);
            wmma::fill_fragment(p1, 0.0f);
#pragma unroll
            for (int kk = 0; kk < BKV; kk += 8) {
                wmma::fragment<wmma::matrix_a, 16, 16, 8, wmma::precision::tf32,
                               wmma::row_major> a;
                wmma::fragment<wmma::matrix_b, 16, 16, 8, wmma::precision::tf32,
                               wmma::col_major> b0, b1;
                wmma::load_matrix_sync(a, Ss + (wm * 16) * FLD + kk, FLD);
                wmma::load_matrix_sync(b0, Vt + (wn * 32) * FLD + kk, FLD);
                wmma::load_matrix_sync(b1, Vt + (wn * 32 + 16) * FLD + kk, FLD);
                wmma::mma_sync(p0, a, b0, p0);
                wmma::mma_sync(p1, a, b1, p1);
            }
            wmma::store_matrix_sync(PVs + (wm * 16) * FLD + wn * 32, p0, FLD,
                                    wmma::mem_row_major);
            wmma::store_matrix_sync(PVs + (wm * 16) * FLD + wn * 32 + 16, p1, FLD,
                                    wmma::mem_row_major);
        }
        __syncthreads();

        // O = O*corr + PV
#pragma unroll
        for (int c = 0; c < 16; ++c)
            o[c] = o[c] * corr + PVs[row * FLD + cbase + c];
        __syncthreads();
    }

    float linv = 1.f / lrow[row];
#pragma unroll
    for (int c = 0; c < 16; ++c) {
        g_ctx[((size_t)b * SEQ + q0 + row) * D_MODEL + h * DK + cbase + c] =
            rtf32(o[c] * linv);
    }
}

// ---------------------------------------------------------------------------
extern "C" void kernel_launch(void* const* d_in, const int* in_sizes, int n_in,
                              void* d_out, int out_size)
{
    const float* x  = (const float*)d_in[0];
    const float* Wq = (const float*)d_in[1];
    const float* bq = (const float*)d_in[2];
    const float* Wk = (const float*)d_in[3];
    const float* bk = (const float*)d_in[4];
    const float* Wv = (const float*)d_in[5];
    const float* bv = (const float*)d_in[6];
    const float* Wo = (const float*)d_in[7];
    const float* bo = (const float*)d_in[8];
    float* out = (float*)d_out;

    float *pQ, *pK, *pV, *pCtx, *pXr, *pWr;
    cudaGetSymbolAddress((void**)&pQ, g_Q);
    cudaGetSymbolAddress((void**)&pK, g_K);
    cudaGetSymbolAddress((void**)&pV, g_V);
    cudaGetSymbolAddress((void**)&pCtx, g_ctx);
    cudaGetSymbolAddress((void**)&pXr, g_xr);
    cudaGetSymbolAddress((void**)&pWr, g_Wr);

    cudaFuncSetAttribute(flash_tf32,
                         cudaFuncAttributeMaxDynamicSharedMemorySize,
                         FLASH_SMEM_BYTES);
    cudaFuncSetAttribute(gemm_tf32<true>,
                         cudaFuncAttributeMaxDynamicSharedMemorySize,
                         GEMM_SMEM_BYTES);
    cudaFuncSetAttribute(gemm_tf32<false>,
                         cudaFuncAttributeMaxDynamicSharedMemorySize,
                         GEMM_SMEM_BYTES);

    {
        int tot4 = (NX + 4 * NW) / 4;
        pre_round_kernel<<<(tot4 + 255) / 256, 256>>>(x, Wq, Wk, Wv, Wo);
    }

    dim3 qkvGrid(D_MODEL / 128, M_TOT / 128, 3);   // (8, 32, 3)
    gemm_tf32<true><<<qkvGrid, 256, GEMM_SMEM_BYTES>>>(
        pXr, pWr, pWr + NW, pWr + 2 * NW, bq, bk, bv, pQ, pK, pV);

    dim3 flashGrid(SEQ / BQ, BATCH * N_HEADS);     // (32, 32)
    flash_tf32<<<flashGrid, 256, FLASH_SMEM_BYTES>>>();

    dim3 gemmGrid(D_MODEL / 128, M_TOT / 128, 1);
    gemm_tf32<false><<<gemmGrid, 256, GEMM_SMEM_BYTES>>>(
        pCtx, pWr + 3 * NW, nullptr, nullptr, bo, nullptr, nullptr,
        out, nullptr, nullptr);
}

// round 6
// speedup vs baseline: 3.1769x; 1.1762x over previous
#include <cuda_runtime.h>
#include <cstdint>
#include <mma.h>
#include <math.h>

using namespace nvcuda;

#define D_MODEL 1024
#define N_HEADS 16
#define DK 64
#define BATCH 2
#define SEQ 2048
#define M_TOT (BATCH * SEQ)   // 4096
#define NX (M_TOT * D_MODEL)      // 4,194,304
#define NW (D_MODEL * D_MODEL)    // 1,048,576

__device__ float g_Q[BATCH * N_HEADS * SEQ * DK];   // [B,H,S,dk] tf32-rounded
__device__ float g_K[BATCH * N_HEADS * SEQ * DK];
__device__ float g_V[BATCH * N_HEADS * SEQ * DK];
__device__ float g_ctx[BATCH * SEQ * D_MODEL];      // [B,S,D]    tf32-rounded
__device__ float g_xr[NX];                          // tf32-rounded x
__device__ float g_Wr[4 * NW];                      // tf32-rounded Wq,Wk,Wv,Wo

__device__ __forceinline__ float rtf32(float a) {
    float r;
    asm("cvt.rna.tf32.f32 %0, %1;" : "=f"(r) : "f"(a));
    return r;
}

// fast exp2 on fma/alu pipes (no MUFU). Inputs <= 0.
__device__ __forceinline__ float fexp2(float x) {
    x = fmaxf(x, -126.0f);
    float r = rintf(x);
    float f = x - r;                       // [-0.5, 0.5]
    float p = 1.3333558e-3f;
    p = fmaf(p, f, 9.6181291e-3f);
    p = fmaf(p, f, 5.5504109e-2f);
    p = fmaf(p, f, 2.4022651e-1f);
    p = fmaf(p, f, 6.9314718e-1f);
    p = fmaf(p, f, 1.0f);
    return __int_as_float(__float_as_int(p) + (((int)r) << 23));
}

__device__ __forceinline__ void cp_async16(unsigned smem_dst, const float* gmem_src) {
    asm volatile("cp.async.cg.shared.global [%0], [%1], 16;\n"
                 :: "r"(smem_dst), "l"(gmem_src));
}

// ---------------------------------------------------------------------------
// Pre-round x and weights to tf32 once.
// ---------------------------------------------------------------------------
__global__ __launch_bounds__(256)
void pre_round_kernel(const float* __restrict__ x,
                      const float* __restrict__ Wq, const float* __restrict__ Wk,
                      const float* __restrict__ Wv, const float* __restrict__ Wo)
{
    int i4 = blockIdx.x * blockDim.x + threadIdx.x;
    const int tot4 = (NX + 4 * NW) / 4;
    if (i4 >= tot4) return;
    int i = i4 * 4;
    const float* src;
    float* dst;
    if (i < NX) { src = x + i; dst = g_xr + i; }
    else {
        int j = i - NX;
        int t = j / NW;
        int o = j - t * NW;
        src = (t == 0 ? Wq : t == 1 ? Wk : t == 2 ? Wv : Wo) + o;
        dst = g_Wr + j;
    }
    float4 v = *(const float4*)src;
    v.x = rtf32(v.x); v.y = rtf32(v.y); v.z = rtf32(v.z); v.w = rtf32(v.w);
    *(float4*)dst = v;
}

// ---------------------------------------------------------------------------
// TF32 wmma GEMM, cp.async 2-stage: C = A[M,K] @ W[N,K]^T + bias[N]
// Block 128(M) x 256(N), BK=32. 8 warps as 2x4, warp tile 64x64.
// 16 mma per 8-k chunk per warp vs 8 fragment loads.
// ---------------------------------------------------------------------------
#define GLDA 36
#define SLDA 20
#define A_STG (128 * GLDA)        // one A stage (floats)
#define B_STG (256 * GLDA)        // one B stage
#define GEMM_SMEM_FLOATS (2 * A_STG + 2 * B_STG)
#define GEMM_SMEM_BYTES (GEMM_SMEM_FLOATS * 4)

template <bool QKV>
__global__ __launch_bounds__(256)
void gemm_tf32(const float* __restrict__ A,
               const float* __restrict__ W0, const float* __restrict__ W1,
               const float* __restrict__ W2,
               const float* __restrict__ b0, const float* __restrict__ b1,
               const float* __restrict__ b2,
               float* __restrict__ C0, float* __restrict__ C1,
               float* __restrict__ C2)
{
    extern __shared__ float smg[];
    float* As = smg;                 // 2 stages x 128 x GLDA
    float* Bs = As + 2 * A_STG;      // 2 stages x 256 x GLDA

    const float* W; const float* bias; float* C;
    if (QKV) {
        int z = blockIdx.z;
        W = (z == 0) ? W0 : (z == 1) ? W1 : W2;
        bias = (z == 0) ? b0 : (z == 1) ? b1 : b2;
        C = (z == 0) ? C0 : (z == 1) ? C1 : C2;
    } else { W = W0; bias = b0; C = C0; }

    const int tid = threadIdx.x;
    const int warpId = tid >> 5;
    const int lane = tid & 31;
    const int wm = warpId & 1;       // 0..1 -> 64-row slab
    const int wn = warpId >> 1;      // 0..3 -> 64-col slab
    const int blockRow = blockIdx.y * 128;
    const int blockCol = blockIdx.x * 256;

    const unsigned As_u = (unsigned)__cvta_generic_to_shared(As);
    const unsigned Bs_u = (unsigned)__cvta_generic_to_shared(Bs);

    wmma::fragment<wmma::accumulator, 16, 16, 8, float> acc[4][4];
#pragma unroll
    for (int i = 0; i < 4; ++i)
#pragma unroll
        for (int j = 0; j < 4; ++j) wmma::fill_fragment(acc[i][j], 0.0f);

    auto load_stage = [&](int s, int k0) {
#pragma unroll
        for (int l = 0; l < 4; ++l) {             // A: 1024 float4
            int id = tid + l * 256;
            int row = id >> 3;                    // 0..127
            int c4 = (id & 7) * 4;
            unsigned off = (unsigned)((s * A_STG + row * GLDA + c4) * 4);
            cp_async16(As_u + off, A + (size_t)(blockRow + row) * D_MODEL + k0 + c4);
        }
#pragma unroll
        for (int l = 0; l < 8; ++l) {             // B: 2048 float4
            int id = tid + l * 256;
            int row = id >> 3;                    // 0..255
            int c4 = (id & 7) * 4;
            unsigned off = (unsigned)((s * B_STG + row * GLDA + c4) * 4);
            cp_async16(Bs_u + off, W + (size_t)(blockCol + row) * D_MODEL + k0 + c4);
        }
        asm volatile("cp.async.commit_group;\n" ::);
    };

    load_stage(0, 0);

    const int NT = D_MODEL / 32;
    for (int t = 0; t < NT; ++t) {
        if (t + 1 < NT) {
            load_stage((t + 1) & 1, (t + 1) * 32);
            asm volatile("cp.async.wait_group 1;\n" ::);
        } else {
            asm volatile("cp.async.wait_group 0;\n" ::);
        }
        __syncthreads();

        const float* Asb = As + (t & 1) * A_STG;
        const float* Bsb = Bs + (t & 1) * B_STG;
#pragma unroll
        for (int kk = 0; kk < 32; kk += 8) {
            wmma::fragment<wmma::matrix_a, 16, 16, 8, wmma::precision::tf32,
                           wmma::row_major> a[4];
            wmma::fragment<wmma::matrix_b, 16, 16, 8, wmma::precision::tf32,
                           wmma::col_major> b[4];
#pragma unroll
            for (int i = 0; i < 4; ++i)
                wmma::load_matrix_sync(a[i], Asb + (wm * 64 + i * 16) * GLDA + kk, GLDA);
#pragma unroll
            for (int j = 0; j < 4; ++j)
                wmma::load_matrix_sync(b[j], Bsb + (wn * 64 + j * 16) * GLDA + kk, GLDA);
#pragma unroll
            for (int i = 0; i < 4; ++i)
#pragma unroll
                for (int j = 0; j < 4; ++j)
                    wmma::mma_sync(acc[i][j], a[i], b[j], acc[i][j]);
        }
        __syncthreads();
    }

    // Epilogue: stage 16x16 tiles through smem (aliases As), add bias, scatter.
    float* stg = As + warpId * 16 * SLDA;
#pragma unroll
    for (int i = 0; i < 4; ++i) {
#pragma unroll
        for (int j = 0; j < 4; ++j) {
            wmma::store_matrix_sync(stg, acc[i][j], SLDA, wmma::mem_row_major);
            __syncwarp();
            int r = lane >> 1;
            int cb = (lane & 1) * 8;
            int m = blockRow + wm * 64 + i * 16 + r;
#pragma unroll
            for (int c = 0; c < 8; ++c) {
                int n = blockCol + wn * 64 + j * 16 + cb + c;
                float val = stg[r * SLDA + cb + c] + __ldg(&bias[n]);
                if (QKV) {
                    int b_ = m / SEQ;
                    int s_ = m - b_ * SEQ;
                    int h_ = n / DK;
                    int d_ = n - h_ * DK;
                    C[(((size_t)(b_ * N_HEADS + h_) * SEQ) + s_) * DK + d_] = rtf32(val);
                } else {
                    C[(size_t)m * D_MODEL + n] = val;
                }
            }
            __syncwarp();
        }
    }
}

// ---------------------------------------------------------------------------
// Causal flash attention, TF32 wmma, poly-exp2 softmax.
// cp.async double-buffered K/V; Q persistent in matrix_a fragments;
// V untransposed (row_major matrix_b); Qs aliased as PVs. 4 barriers/iter.
// ---------------------------------------------------------------------------
#define BQ 64
#define BKV 64
#define FLD 68
#define KV_STG (64 * FLD)
// layout: Ks[2] | Vs[2] | Ss | QPV | stats
#define FLASH_SMEM_FLOATS (4 * KV_STG + 2 * KV_STG + 128)
#define FLASH_SMEM_BYTES (FLASH_SMEM_FLOATS * 4)

__global__ __launch_bounds__(256, 2)
void flash_tf32()
{
    extern __shared__ float sm[];
    float* Ks  = sm;                      // 2 x [64][FLD]
    float* Vs  = Ks + 2 * KV_STG;         // 2 x [64][FLD]
    float* Ss  = Vs + 2 * KV_STG;         // [64][FLD] scores -> P
    float* QPV = Ss + KV_STG;             // Q staging, then PV tile
    float* mrow = QPV + KV_STG;           // [64]
    float* lrow = mrow + 64;              // [64]

    const int bh = blockIdx.y;
    const int qt = blockIdx.x;
    const int b = bh / N_HEADS;
    const int h = bh - b * N_HEADS;

    const float* Qg = g_Q + (size_t)bh * SEQ * DK;
    const float* Kg = g_K + (size_t)bh * SEQ * DK;
    const float* Vg = g_V + (size_t)bh * SEQ * DK;

    const int tid = threadIdx.x;
    const int warpId = tid >> 5;
    const int wm = warpId & 3;            // rows wm*16..+15
    const int wn = warpId >> 2;           // cols wn*32..+31
    const int q0 = qt * BQ;

    const int row = tid >> 2;
    const int part = tid & 3;
    const int cbase = part * 16;
    const int qi = q0 + row;

    const unsigned Ks_u = (unsigned)__cvta_generic_to_shared(Ks);
    const unsigned Vs_u = (unsigned)__cvta_generic_to_shared(Vs);

    const float qscale = 0.125f * 1.44269504089f;  // scale * log2(e)

    // prefetch KV tile 0
    auto prefetch_kv = [&](int kt) {
        int k0 = kt * BKV;
        unsigned sbase = (unsigned)((kt & 1) * KV_STG * 4);
#pragma unroll
        for (int l = 0; l < 4; ++l) {
            int id = tid + l * 256;
            int r = id >> 4;
            int c4 = (id & 15) * 4;
            unsigned off = sbase + (unsigned)((r * FLD + c4) * 4);
            cp_async16(Ks_u + off, Kg + (size_t)(k0 + r) * DK + c4);
            cp_async16(Vs_u + off, Vg + (size_t)(k0 + r) * DK + c4);
        }
        asm volatile("cp.async.commit_group;\n" ::);
    };
    prefetch_kv(0);

    // stage Q into QPV (scaled), then hoist to persistent fragments
#pragma unroll
    for (int l = 0; l < 4; ++l) {
        int id = tid + l * 256;
        int r = id >> 4;
        int c4 = (id & 15) * 4;
        float4 v = *(const float4*)(Qg + (size_t)(q0 + r) * DK + c4);
        v.x = rtf32(v.x * qscale); v.y = rtf32(v.y * qscale);
        v.z = rtf32(v.z * qscale); v.w = rtf32(v.w * qscale);
        *(float4*)(QPV + r * FLD + c4) = v;
    }
    if (tid < 64) { mrow[tid] = -1e30f; lrow[tid] = 0.f; }
    __syncthreads();

    wmma::fragment<wmma::matrix_a, 16, 16, 8, wmma::precision::tf32,
                   wmma::row_major> qf[8];           // 64 k in 8 chunks
#pragma unroll
    for (int kk = 0; kk < 8; ++kk)
        wmma::load_matrix_sync(qf[kk], QPV + (wm * 16) * FLD + kk * 8, FLD);

    float o[16];
#pragma unroll
    for (int c = 0; c < 16; ++c) o[c] = 0.f;

    for (int kt = 0; kt <= qt; ++kt) {
        if (kt + 1 <= qt) {
            prefetch_kv(kt + 1);
            asm volatile("cp.async.wait_group 1;\n" ::);
        } else {
            asm volatile("cp.async.wait_group 0;\n" ::);
        }
        __syncthreads();                          // B1: KV[kt] visible

        const float* Kb = Ks + (kt & 1) * KV_STG;
        const float* Vb = Vs + (kt & 1) * KV_STG;
        const int k0 = kt * BKV;

        // S = Q @ K^T
        {
            wmma::fragment<wmma::accumulator, 16, 16, 8, float> s0, s1;
            wmma::fill_fragment(s0, 0.0f);
            wmma::fill_fragment(s1, 0.0f);
#pragma unroll
            for (int kk = 0; kk < 8; ++kk) {
                wmma::fragment<wmma::matrix_b, 16, 16, 8, wmma::precision::tf32,
                               wmma::col_major> b0, b1;
                wmma::load_matrix_sync(b0, Kb + (wn * 32) * FLD + kk * 8, FLD);
                wmma::load_matrix_sync(b1, Kb + (wn * 32 + 16) * FLD + kk * 8, FLD);
                wmma::mma_sync(s0, qf[kk], b0, s0);
                wmma::mma_sync(s1, qf[kk], b1, s1);
            }
            wmma::store_matrix_sync(Ss + (wm * 16) * FLD + wn * 32, s0, FLD,
                                    wmma::mem_row_major);
            wmma::store_matrix_sync(Ss + (wm * 16) * FLD + wn * 32 + 16, s1, FLD,
                                    wmma::mem_row_major);
        }
        __syncthreads();                          // B2: Ss ready

        // online softmax (base-2), 4 threads per row
        float corr;
        {
            float vals[16];
            float mloc = -1e30f;
#pragma unroll
            for (int c = 0; c < 16; ++c) {
                int kj = k0 + cbase + c;
                float v = (kj <= qi) ? Ss[row * FLD + cbase + c] : -1e30f;
                vals[c] = v;
                mloc = fmaxf(mloc, v);
            }
            mloc = fmaxf(mloc, __shfl_xor_sync(0xFFFFFFFF, mloc, 1));
            mloc = fmaxf(mloc, __shfl_xor_sync(0xFFFFFFFF, mloc, 2));
            float mold = mrow[row];
            float lold = lrow[row];
            __syncwarp();
            float mnew = fmaxf(mold, mloc);
            float suml = 0.f;
#pragma unroll
            for (int c = 0; c < 16; ++c) {
                float p = fexp2(vals[c] - mnew);
                Ss[row * FLD + cbase + c] = rtf32(p);
                suml += p;
            }
            suml += __shfl_xor_sync(0xFFFFFFFF, suml, 1);
            suml += __shfl_xor_sync(0xFFFFFFFF, suml, 2);
            corr = fexp2(mold - mnew);
            if (part == 0) {
                mrow[row] = mnew;
                lrow[row] = lold * corr + suml;
            }
        }
        __syncthreads();                          // B3: P ready

        // PV = P @ V  (V untransposed: row_major matrix_b over kv)
        {
            wmma::fragment<wmma::accumulator, 16, 16, 8, float> p0, p1;
            wmma::fill_fragment(p0, 0.0f);
            wmma::fill_fragment(p1, 0.0f);
#pragma unroll
            for (int kk = 0; kk < 8; ++kk) {
                wmma::fragment<wmma::matrix_a, 16, 16, 8, wmma::precision::tf32,
                               wmma::row_major> a;
                wmma::fragment<wmma::matrix_b, 16, 16, 8, wmma::precision::tf32,
                               wmma::row_major> b0, b1;
                wmma::load_matrix_sync(a, Ss + (wm * 16) * FLD + kk * 8, FLD);
                wmma::load_matrix_sync(b0, Vb + (kk * 8) * FLD + wn * 32, FLD);
                wmma::load_matrix_sync(b1, Vb + (kk * 8) * FLD + wn * 32 + 16, FLD);
                wmma::mma_sync(p0, a, b0, p0);
                wmma::mma_sync(p1, a, b1, p1);
            }
            wmma::store_matrix_sync(QPV + (wm * 16) * FLD + wn * 32, p0, FLD,
                                    wmma::mem_row_major);
            wmma::store_matrix_sync(QPV + (wm * 16) * FLD + wn * 32 + 16, p1, FLD,
                                    wmma::mem_row_major);
        }
        __syncthreads();                          // B4: PV ready

        // O = O*corr + PV  (next iter's B1 protects buffers)
#pragma unroll
        for (int c = 0; c < 16; ++c)
            o[c] = o[c] * corr + QPV[row * FLD + cbase + c];
    }

    float linv = 1.f / lrow[row];
#pragma unroll
    for (int c = 0; c < 16; ++c) {
        g_ctx[((size_t)b * SEQ + q0 + row) * D_MODEL + h * DK + cbase + c] =
            rtf32(o[c] * linv);
    }
}

// ---------------------------------------------------------------------------
extern "C" void kernel_launch(void* const* d_in, const int* in_sizes, int n_in,
                              void* d_out, int out_size)
{
    const float* x  = (const float*)d_in[0];
    const float* Wq = (const float*)d_in[1];
    const float* bq = (const float*)d_in[2];
    const float* Wk = (const float*)d_in[3];
    const float* bk = (const float*)d_in[4];
    const float* Wv = (const float*)d_in[5];
    const float* bv = (const float*)d_in[6];
    const float* Wo = (const float*)d_in[7];
    const float* bo = (const float*)d_in[8];
    float* out = (float*)d_out;

    float *pQ, *pK, *pV, *pCtx, *pXr, *pWr;
    cudaGetSymbolAddress((void**)&pQ, g_Q);
    cudaGetSymbolAddress((void**)&pK, g_K);
    cudaGetSymbolAddress((void**)&pV, g_V);
    cudaGetSymbolAddress((void**)&pCtx, g_ctx);
    cudaGetSymbolAddress((void**)&pXr, g_xr);
    cudaGetSymbolAddress((void**)&pWr, g_Wr);

    cudaFuncSetAttribute(flash_tf32,
                         cudaFuncAttributeMaxDynamicSharedMemorySize,
                         FLASH_SMEM_BYTES);
    cudaFuncSetAttribute(gemm_tf32<true>,
                         cudaFuncAttributeMaxDynamicSharedMemorySize,
                         GEMM_SMEM_BYTES);
    cudaFuncSetAttribute(gemm_tf32<false>,
                         cudaFuncAttributeMaxDynamicSharedMemorySize,
                         GEMM_SMEM_BYTES);

    {
        int tot4 = (NX + 4 * NW) / 4;
        pre_round_kernel<<<(tot4 + 255) / 256, 256>>>(x, Wq, Wk, Wv, Wo);
    }

    dim3 qkvGrid(D_MODEL / 256, M_TOT / 128, 3);   // (4, 32, 3)
    gemm_tf32<true><<<qkvGrid, 256, GEMM_SMEM_BYTES>>>(
        pXr, pWr, pWr + NW, pWr + 2 * NW, bq, bk, bv, pQ, pK, pV);

    dim3 flashGrid(SEQ / BQ, BATCH * N_HEADS);     // (32, 32)
    flash_tf32<<<flashGrid, 256, FLASH_SMEM_BYTES>>>();

    dim3 gemmGrid(D_MODEL / 256, M_TOT / 128, 1);  // (4, 32)
    gemm_tf32<false><<<gemmGrid, 256, GEMM_SMEM_BYTES>>>(
        pCtx, pWr + 3 * NW, nullptr, nullptr, bo, nullptr, nullptr,
        out, nullptr, nullptr);
}

// round 7
// speedup vs baseline: 3.3616x; 1.0582x over previous
#include <cuda_runtime.h>
#include <cstdint>
#include <mma.h>
#include <math.h>

using namespace nvcuda;

#define D_MODEL 1024
#define N_HEADS 16
#define DK 64
#define BATCH 2
#define SEQ 2048
#define M_TOT (BATCH * SEQ)   // 4096
#define NX (M_TOT * D_MODEL)      // 4,194,304
#define NW (D_MODEL * D_MODEL)    // 1,048,576

__device__ float g_Q[BATCH * N_HEADS * SEQ * DK];   // [B,H,S,dk] tf32-rounded
__device__ float g_K[BATCH * N_HEADS * SEQ * DK];
__device__ float g_V[BATCH * N_HEADS * SEQ * DK];
__device__ float g_ctx[BATCH * SEQ * D_MODEL];      // [B,S,D]    tf32-rounded
__device__ float g_xr[NX];                          // tf32-rounded x
__device__ float g_Wr[4 * NW];                      // tf32-rounded Wq,Wk,Wv,Wo

__device__ __forceinline__ float rtf32(float a) {
    float r;
    asm("cvt.rna.tf32.f32 %0, %1;" : "=f"(r) : "f"(a));
    return r;
}

// fast exp2 on fma/alu pipes (no MUFU). Inputs <= 0.
__device__ __forceinline__ float fexp2(float x) {
    x = fmaxf(x, -126.0f);
    float r = rintf(x);
    float f = x - r;                       // [-0.5, 0.5]
    float p = 1.3333558e-3f;
    p = fmaf(p, f, 9.6181291e-3f);
    p = fmaf(p, f, 5.5504109e-2f);
    p = fmaf(p, f, 2.4022651e-1f);
    p = fmaf(p, f, 6.9314718e-1f);
    p = fmaf(p, f, 1.0f);
    return __int_as_float(__float_as_int(p) + (((int)r) << 23));
}

__device__ __forceinline__ void cp_async16(unsigned smem_dst, const float* gmem_src) {
    asm volatile("cp.async.cg.shared.global [%0], [%1], 16;\n"
                 :: "r"(smem_dst), "l"(gmem_src));
}

// ---------------------------------------------------------------------------
// Pre-round x and weights to tf32 once.
// ---------------------------------------------------------------------------
__global__ __launch_bounds__(256)
void pre_round_kernel(const float* __restrict__ x,
                      const float* __restrict__ Wq, const float* __restrict__ Wk,
                      const float* __restrict__ Wv, const float* __restrict__ Wo)
{
    int i4 = blockIdx.x * blockDim.x + threadIdx.x;
    const int tot4 = (NX + 4 * NW) / 4;
    if (i4 >= tot4) return;
    int i = i4 * 4;
    const float* src;
    float* dst;
    if (i < NX) { src = x + i; dst = g_xr + i; }
    else {
        int j = i - NX;
        int t = j / NW;
        int o = j - t * NW;
        src = (t == 0 ? Wq : t == 1 ? Wk : t == 2 ? Wv : Wo) + o;
        dst = g_Wr + j;
    }
    float4 v = *(const float4*)src;
    v.x = rtf32(v.x); v.y = rtf32(v.y); v.z = rtf32(v.z); v.w = rtf32(v.w);
    *(float4*)dst = v;
}

// ---------------------------------------------------------------------------
// TF32 wmma GEMM, cp.async 3-stage, 1 barrier/iter:
// C = A[M,K] @ W[N,K]^T + bias[N]. Block 128x256, BK=32, 8 warps, 64x64 tiles.
// ---------------------------------------------------------------------------
#define GLDA 36
#define SLDA 20
#define A_STG (128 * GLDA)
#define B_STG (256 * GLDA)
#define GEMM_SMEM_FLOATS (3 * A_STG + 3 * B_STG)
#define GEMM_SMEM_BYTES (GEMM_SMEM_FLOATS * 4)

template <bool QKV>
__global__ __launch_bounds__(256)
void gemm_tf32(const float* __restrict__ A,
               const float* __restrict__ W0, const float* __restrict__ W1,
               const float* __restrict__ W2,
               const float* __restrict__ b0, const float* __restrict__ b1,
               const float* __restrict__ b2,
               float* __restrict__ C0, float* __restrict__ C1,
               float* __restrict__ C2)
{
    extern __shared__ float smg[];
    float* As = smg;                 // 3 stages x 128 x GLDA
    float* Bs = As + 3 * A_STG;      // 3 stages x 256 x GLDA

    const float* W; const float* bias; float* C;
    if (QKV) {
        int z = blockIdx.z;
        W = (z == 0) ? W0 : (z == 1) ? W1 : W2;
        bias = (z == 0) ? b0 : (z == 1) ? b1 : b2;
        C = (z == 0) ? C0 : (z == 1) ? C1 : C2;
    } else { W = W0; bias = b0; C = C0; }

    const int tid = threadIdx.x;
    const int warpId = tid >> 5;
    const int lane = tid & 31;
    const int wm = warpId & 1;
    const int wn = warpId >> 1;
    const int blockRow = blockIdx.y * 128;
    const int blockCol = blockIdx.x * 256;

    const unsigned As_u = (unsigned)__cvta_generic_to_shared(As);
    const unsigned Bs_u = (unsigned)__cvta_generic_to_shared(Bs);

    wmma::fragment<wmma::accumulator, 16, 16, 8, float> acc[4][4];
#pragma unroll
    for (int i = 0; i < 4; ++i)
#pragma unroll
        for (int j = 0; j < 4; ++j) wmma::fill_fragment(acc[i][j], 0.0f);

    auto load_stage = [&](int s, int k0) {
#pragma unroll
        for (int l = 0; l < 4; ++l) {             // A: 1024 float4
            int id = tid + l * 256;
            int row = id >> 3;
            int c4 = (id & 7) * 4;
            unsigned off = (unsigned)((s * A_STG + row * GLDA + c4) * 4);
            cp_async16(As_u + off, A + (size_t)(blockRow + row) * D_MODEL + k0 + c4);
        }
#pragma unroll
        for (int l = 0; l < 8; ++l) {             // B: 2048 float4
            int id = tid + l * 256;
            int row = id >> 3;
            int c4 = (id & 7) * 4;
            unsigned off = (unsigned)((s * B_STG + row * GLDA + c4) * 4);
            cp_async16(Bs_u + off, W + (size_t)(blockCol + row) * D_MODEL + k0 + c4);
        }
        asm volatile("cp.async.commit_group;\n" ::);
    };

    load_stage(0, 0);
    load_stage(1, 32);

    const int NT = D_MODEL / 32;
    for (int t = 0; t < NT; ++t) {
        if (t + 1 < NT) {
            asm volatile("cp.async.wait_group 1;\n" ::);
        } else {
            asm volatile("cp.async.wait_group 0;\n" ::);
        }
        __syncthreads();                      // stage t visible to all

        if (t + 2 < NT)                       // overwrites stage t-1 (all done)
            load_stage((t + 2) % 3, (t + 2) * 32);

        const float* Asb = As + (t % 3) * A_STG;
        const float* Bsb = Bs + (t % 3) * B_STG;
#pragma unroll
        for (int kk = 0; kk < 32; kk += 8) {
            wmma::fragment<wmma::matrix_a, 16, 16, 8, wmma::precision::tf32,
                           wmma::row_major> a[4];
            wmma::fragment<wmma::matrix_b, 16, 16, 8, wmma::precision::tf32,
                           wmma::col_major> b[4];
#pragma unroll
            for (int i = 0; i < 4; ++i)
                wmma::load_matrix_sync(a[i], Asb + (wm * 64 + i * 16) * GLDA + kk, GLDA);
#pragma unroll
            for (int j = 0; j < 4; ++j)
                wmma::load_matrix_sync(b[j], Bsb + (wn * 64 + j * 16) * GLDA + kk, GLDA);
#pragma unroll
            for (int i = 0; i < 4; ++i)
#pragma unroll
                for (int j = 0; j < 4; ++j)
                    wmma::mma_sync(acc[i][j], a[i], b[j], acc[i][j]);
        }
    }
    __syncthreads();

    // Epilogue: stage 16x16 tiles through smem (aliases As stage 0).
    float* stg = As + warpId * 16 * SLDA;
#pragma unroll
    for (int i = 0; i < 4; ++i) {
#pragma unroll
        for (int j = 0; j < 4; ++j) {
            wmma::store_matrix_sync(stg, acc[i][j], SLDA, wmma::mem_row_major);
            __syncwarp();
            int r = lane >> 1;
            int cb = (lane & 1) * 8;
            int m = blockRow + wm * 64 + i * 16 + r;
#pragma unroll
            for (int c = 0; c < 8; ++c) {
                int n = blockCol + wn * 64 + j * 16 + cb + c;
                float val = stg[r * SLDA + cb + c] + __ldg(&bias[n]);
                if (QKV) {
                    int b_ = m / SEQ;
                    int s_ = m - b_ * SEQ;
                    int h_ = n / DK;
                    int d_ = n - h_ * DK;
                    C[(((size_t)(b_ * N_HEADS + h_) * SEQ) + s_) * DK + d_] = rtf32(val);
                } else {
                    C[(size_t)m * D_MODEL + n] = val;
                }
            }
            __syncwarp();
        }
    }
}

// ---------------------------------------------------------------------------
// Causal flash attention, TF32 wmma. 128 threads = 4 warps, warp tile 32x32
// (mma:load = 1.0). 2 CTAs/SM. cp.async double-buffered K/V, Q persistent
// in fragments, V row_major, poly-exp2 softmax 2 threads/row.
// ---------------------------------------------------------------------------
#define BQ 64
#define BKV 64
#define FLD 68
#define KV_STG (64 * FLD)
#define FLASH_SMEM_FLOATS (4 * KV_STG + 2 * KV_STG + 128)
#define FLASH_SMEM_BYTES (FLASH_SMEM_FLOATS * 4)

__global__ __launch_bounds__(128, 2)
void flash_tf32()
{
    extern __shared__ float sm[];
    float* Ks  = sm;                      // 2 x [64][FLD]
    float* Vs  = Ks + 2 * KV_STG;         // 2 x [64][FLD]
    float* Ss  = Vs + 2 * KV_STG;         // [64][FLD] scores -> P
    float* QPV = Ss + KV_STG;             // Q staging, then PV tile
    float* mrow = QPV + KV_STG;           // [64]
    float* lrow = mrow + 64;              // [64]

    const int bh = blockIdx.y;
    const int qt = blockIdx.x;
    const int b = bh / N_HEADS;
    const int h = bh - b * N_HEADS;

    const float* Qg = g_Q + (size_t)bh * SEQ * DK;
    const float* Kg = g_K + (size_t)bh * SEQ * DK;
    const float* Vg = g_V + (size_t)bh * SEQ * DK;

    const int tid = threadIdx.x;
    const int warpId = tid >> 5;
    const int wm = warpId & 1;            // rows wm*32..+31
    const int wn = warpId >> 1;           // cols wn*32..+31
    const int q0 = qt * BQ;

    const int row = tid >> 1;             // 0..63
    const int part = tid & 1;
    const int cbase = part * 32;
    const int qi = q0 + row;

    const unsigned Ks_u = (unsigned)__cvta_generic_to_shared(Ks);
    const unsigned Vs_u = (unsigned)__cvta_generic_to_shared(Vs);

    const float qscale = 0.125f * 1.44269504089f;  // scale * log2(e)

    auto prefetch_kv = [&](int kt) {
        int k0 = kt * BKV;
        unsigned sbase = (unsigned)((kt & 1) * KV_STG * 4);
#pragma unroll
        for (int l = 0; l < 8; ++l) {
            int id = tid + l * 128;
            int r = id >> 4;
            int c4 = (id & 15) * 4;
            unsigned off = sbase + (unsigned)((r * FLD + c4) * 4);
            cp_async16(Ks_u + off, Kg + (size_t)(k0 + r) * DK + c4);
            cp_async16(Vs_u + off, Vg + (size_t)(k0 + r) * DK + c4);
        }
        asm volatile("cp.async.commit_group;\n" ::);
    };
    prefetch_kv(0);

    // stage Q (scaled) into QPV, hoist into persistent fragments
#pragma unroll
    for (int l = 0; l < 8; ++l) {
        int id = tid + l * 128;
        int r = id >> 4;
        int c4 = (id & 15) * 4;
        float4 v = *(const float4*)(Qg + (size_t)(q0 + r) * DK + c4);
        v.x = rtf32(v.x * qscale); v.y = rtf32(v.y * qscale);
        v.z = rtf32(v.z * qscale); v.w = rtf32(v.w * qscale);
        *(float4*)(QPV + r * FLD + c4) = v;
    }
    if (tid < 64) { mrow[tid] = -1e30f; lrow[tid] = 0.f; }
    __syncthreads();

    wmma::fragment<wmma::matrix_a, 16, 16, 8, wmma::precision::tf32,
                   wmma::row_major> qf[2][8];
#pragma unroll
    for (int i = 0; i < 2; ++i)
#pragma unroll
        for (int kk = 0; kk < 8; ++kk)
            wmma::load_matrix_sync(qf[i][kk],
                                   QPV + (wm * 32 + i * 16) * FLD + kk * 8, FLD);

    float o[32];
#pragma unroll
    for (int c = 0; c < 32; ++c) o[c] = 0.f;

    for (int kt = 0; kt <= qt; ++kt) {
        if (kt + 1 <= qt) {
            prefetch_kv(kt + 1);
            asm volatile("cp.async.wait_group 1;\n" ::);
        } else {
            asm volatile("cp.async.wait_group 0;\n" ::);
        }
        __syncthreads();                          // B1: KV[kt] visible

        const float* Kb = Ks + (kt & 1) * KV_STG;
        const float* Vb = Vs + (kt & 1) * KV_STG;
        const int k0 = kt * BKV;

        // S = Q @ K^T  (warp 32x32)
        {
            wmma::fragment<wmma::accumulator, 16, 16, 8, float> s[2][2];
#pragma unroll
            for (int i = 0; i < 2; ++i)
#pragma unroll
                for (int j = 0; j < 2; ++j) wmma::fill_fragment(s[i][j], 0.0f);
#pragma unroll
            for (int kk = 0; kk < 8; ++kk) {
                wmma::fragment<wmma::matrix_b, 16, 16, 8, wmma::precision::tf32,
                               wmma::col_major> b0, b1;
                wmma::load_matrix_sync(b0, Kb + (wn * 32) * FLD + kk * 8, FLD);
                wmma::load_matrix_sync(b1, Kb + (wn * 32 + 16) * FLD + kk * 8, FLD);
#pragma unroll
                for (int i = 0; i < 2; ++i) {
                    wmma::mma_sync(s[i][0], qf[i][kk], b0, s[i][0]);
                    wmma::mma_sync(s[i][1], qf[i][kk], b1, s[i][1]);
                }
            }
#pragma unroll
            for (int i = 0; i < 2; ++i)
#pragma unroll
                for (int j = 0; j < 2; ++j)
                    wmma::store_matrix_sync(
                        Ss + (wm * 32 + i * 16) * FLD + wn * 32 + j * 16,
                        s[i][j], FLD, wmma::mem_row_major);
        }
        __syncthreads();                          // B2: Ss ready

        // online softmax (base-2), 2 threads per row
        float corr;
        {
            float vals[32];
            float mloc = -1e30f;
#pragma unroll
            for (int c = 0; c < 32; ++c) {
                int kj = k0 + cbase + c;
                float v = (kj <= qi) ? Ss[row * FLD + cbase + c] : -1e30f;
                vals[c] = v;
                mloc = fmaxf(mloc, v);
            }
            mloc = fmaxf(mloc, __shfl_xor_sync(0xFFFFFFFF, mloc, 1));
            float mold = mrow[row];
            float lold = lrow[row];
            __syncwarp();
            float mnew = fmaxf(mold, mloc);
            float suml = 0.f;
#pragma unroll
            for (int c = 0; c < 32; ++c) {
                float p = fexp2(vals[c] - mnew);
                Ss[row * FLD + cbase + c] = rtf32(p);
                suml += p;
            }
            suml += __shfl_xor_sync(0xFFFFFFFF, suml, 1);
            corr = fexp2(mold - mnew);
            if (part == 0) {
                mrow[row] = mnew;
                lrow[row] = lold * corr + suml;
            }
        }
        __syncthreads();                          // B3: P ready

        // PV = P @ V  (V row_major over kv)
        {
            wmma::fragment<wmma::accumulator, 16, 16, 8, float> p[2][2];
#pragma unroll
            for (int i = 0; i < 2; ++i)
#pragma unroll
                for (int j = 0; j < 2; ++j) wmma::fill_fragment(p[i][j], 0.0f);
#pragma unroll
            for (int kk = 0; kk < 8; ++kk) {
                wmma::fragment<wmma::matrix_a, 16, 16, 8, wmma::precision::tf32,
                               wmma::row_major> a0, a1;
                wmma::fragment<wmma::matrix_b, 16, 16, 8, wmma::precision::tf32,
                               wmma::row_major> b0, b1;
                wmma::load_matrix_sync(a0, Ss + (wm * 32) * FLD + kk * 8, FLD);
                wmma::load_matrix_sync(a1, Ss + (wm * 32 + 16) * FLD + kk * 8, FLD);
                wmma::load_matrix_sync(b0, Vb + (kk * 8) * FLD + wn * 32, FLD);
                wmma::load_matrix_sync(b1, Vb + (kk * 8) * FLD + wn * 32 + 16, FLD);
                wmma::mma_sync(p[0][0], a0, b0, p[0][0]);
                wmma::mma_sync(p[0][1], a0, b1, p[0][1]);
                wmma::mma_sync(p[1][0], a1, b0, p[1][0]);
                wmma::mma_sync(p[1][1], a1, b1, p[1][1]);
            }
#pragma unroll
            for (int i = 0; i < 2; ++i)
#pragma unroll
                for (int j = 0; j < 2; ++j)
                    wmma::store_matrix_sync(
                        QPV + (wm * 32 + i * 16) * FLD + wn * 32 + j * 16,
                        p[i][j], FLD, wmma::mem_row_major);
        }
        __syncthreads();                          // B4: PV ready

#pragma unroll
        for (int c = 0; c < 32; ++c)
            o[c] = o[c] * corr + QPV[row * FLD + cbase + c];
    }

    float linv = 1.f / lrow[row];
#pragma unroll
    for (int c = 0; c < 32; ++c) {
        g_ctx[((size_t)b * SEQ + q0 + row) * D_MODEL + h * DK + cbase + c] =
            rtf32(o[c] * linv);
    }
}

// ---------------------------------------------------------------------------
extern "C" void kernel_launch(void* const* d_in, const int* in_sizes, int n_in,
                              void* d_out, int out_size)
{
    const float* x  = (const float*)d_in[0];
    const float* Wq = (const float*)d_in[1];
    const float* bq = (const float*)d_in[2];
    const float* Wk = (const float*)d_in[3];
    const float* bk = (const float*)d_in[4];
    const float* Wv = (const float*)d_in[5];
    const float* bv = (const float*)d_in[6];
    const float* Wo = (const float*)d_in[7];
    const float* bo = (const float*)d_in[8];
    float* out = (float*)d_out;

    float *pQ, *pK, *pV, *pCtx, *pXr, *pWr;
    cudaGetSymbolAddress((void**)&pQ, g_Q);
    cudaGetSymbolAddress((void**)&pK, g_K);
    cudaGetSymbolAddress((void**)&pV, g_V);
    cudaGetSymbolAddress((void**)&pCtx, g_ctx);
    cudaGetSymbolAddress((void**)&pXr, g_xr);
    cudaGetSymbolAddress((void**)&pWr, g_Wr);

    cudaFuncSetAttribute(flash_tf32,
                         cudaFuncAttributeMaxDynamicSharedMemorySize,
                         FLASH_SMEM_BYTES);
    cudaFuncSetAttribute(gemm_tf32<true>,
                         cudaFuncAttributeMaxDynamicSharedMemorySize,
                         GEMM_SMEM_BYTES);
    cudaFuncSetAttribute(gemm_tf32<false>,
                         cudaFuncAttributeMaxDynamicSharedMemorySize,
                         GEMM_SMEM_BYTES);

    {
        int tot4 = (NX + 4 * NW) / 4;
        pre_round_kernel<<<(tot4 + 255) / 256, 256>>>(x, Wq, Wk, Wv, Wo);
    }

    dim3 qkvGrid(D_MODEL / 256, M_TOT / 128, 3);   // (4, 32, 3)
    gemm_tf32<true><<<qkvGrid, 256, GEMM_SMEM_BYTES>>>(
        pXr, pWr, pWr + NW, pWr + 2 * NW, bq, bk, bv, pQ, pK, pV);

    dim3 flashGrid(SEQ / BQ, BATCH * N_HEADS);     // (32, 32)
    flash_tf32<<<flashGrid, 128, FLASH_SMEM_BYTES>>>();

    dim3 gemmGrid(D_MODEL / 256, M_TOT / 128, 1);  // (4, 32)
    gemm_tf32<false><<<gemmGrid, 256, GEMM_SMEM_BYTES>>>(
        pCtx, pWr + 3 * NW, nullptr, nullptr, bo, nullptr, nullptr,
        out, nullptr, nullptr);
}